// round 15
// baseline (speedup 1.0000x reference)
#include <cuda_runtime.h>

// StackMemory_9122510536894 — R13 (resubmit #2): 2 timesteps per block.
//
// Degenerate scan (proven): stack row 1 never written => s1 == 0 =>
// out[0,t,0,:] = softmax(W*h_t+b)[0] * sigmoid(D*h_t), rows 1..31 == 0.
//
// R12 (fused, 1 t/block): 61.5us, DRAM 69.8%, occ 52.9% (warp-0 imbalance,
// small-block tail). R13: block handles 2 adjacent t-slabs: warp 0 computes
// c0,c1 in one loop (weights loaded once) + writes both c-regions; warps
// 1..7 stream 6200 zero-float4s (27.7/thread ILP). Predicted 59.3-60.5us.

#define HDIM    400
#define SDEPTH  32
#define TSTEPS  8192
#define NTHREADS 256
#define SLABV   ((SDEPTH * HDIM) / 4)   // 3200 float4 per t-slab
#define NCV     (HDIM / 4)              // 100 float4 c-region
#define ZTHREADS (NTHREADS - 32)        // 224 zero-wall threads

__global__ __launch_bounds__(NTHREADS) void StackMemory_kernel(
    const float* __restrict__ hs,   // [T, H]
    const float* __restrict__ W,    // [3, H]
    const float* __restrict__ bv,   // [3]
    const float* __restrict__ Dv,   // [H]
    float* __restrict__ out)        // [T, 32, H]
{
    const int t0  = blockIdx.x * 2;
    const int tid = threadIdx.x;

    float4* __restrict__ o = (float4*)(out + (size_t)t0 * (SDEPTH * HDIM));
    const float4 zv = make_float4(0.f, 0.f, 0.f, 0.f);

    if (tid >= 32) {
        // ---- Warps 1..7: zero walls for both slabs, no dependency ----
        const int zt = tid - 32;            // 0..223
        #pragma unroll
        for (int s = 0; s < 2; ++s) {
            float4* __restrict__ os = o + s * SLABV;
            int i = zt + NCV;               // [100, 3200)
            for (; i + 3 * ZTHREADS < SLABV; i += 4 * ZTHREADS) {
                __stcs(&os[i],               zv);
                __stcs(&os[i +     ZTHREADS], zv);
                __stcs(&os[i + 2 * ZTHREADS], zv);
                __stcs(&os[i + 3 * ZTHREADS], zv);
            }
            for (; i < SLABV; i += ZTHREADS) {
                __stcs(&os[i], zv);
            }
        }
        return;
    }

    // ---- Warp 0: compute c_t0, c_t0+1 in-warp ----
    const int lane = tid;  // 0..31
    const float4* __restrict__ hA = (const float4*)(hs + (size_t)t0 * HDIM);
    const float4* __restrict__ hB = (const float4*)(hs + (size_t)(t0 + 1) * HDIM);
    const float4* __restrict__ W0 = (const float4*)(W);
    const float4* __restrict__ W1 = (const float4*)(W + HDIM);
    const float4* __restrict__ W2 = (const float4*)(W + 2 * HDIM);
    const float4* __restrict__ D4 = (const float4*)(Dv);

    float a0 = 0.f, a1 = 0.f, a2 = 0.f, a3 = 0.f;   // t0 accumulators
    float b0 = 0.f, b1 = 0.f, b2 = 0.f, b3 = 0.f;   // t0+1 accumulators
    for (int j = lane; j < NCV; j += 32) {          // 100 f4: 3-4 per lane
        float4 xa = hA[j];
        float4 xb = hB[j];
        float4 w0 = __ldg(&W0[j]);
        float4 w1 = __ldg(&W1[j]);
        float4 w2 = __ldg(&W2[j]);
        float4 d  = __ldg(&D4[j]);
        a0 = fmaf(xa.x, w0.x, fmaf(xa.y, w0.y, fmaf(xa.z, w0.z, fmaf(xa.w, w0.w, a0))));
        a1 = fmaf(xa.x, w1.x, fmaf(xa.y, w1.y, fmaf(xa.z, w1.z, fmaf(xa.w, w1.w, a1))));
        a2 = fmaf(xa.x, w2.x, fmaf(xa.y, w2.y, fmaf(xa.z, w2.z, fmaf(xa.w, w2.w, a2))));
        a3 = fmaf(xa.x, d.x,  fmaf(xa.y, d.y,  fmaf(xa.z, d.z,  fmaf(xa.w, d.w,  a3))));
        b0 = fmaf(xb.x, w0.x, fmaf(xb.y, w0.y, fmaf(xb.z, w0.z, fmaf(xb.w, w0.w, b0))));
        b1 = fmaf(xb.x, w1.x, fmaf(xb.y, w1.y, fmaf(xb.z, w1.z, fmaf(xb.w, w1.w, b1))));
        b2 = fmaf(xb.x, w2.x, fmaf(xb.y, w2.y, fmaf(xb.z, w2.z, fmaf(xb.w, w2.w, b2))));
        b3 = fmaf(xb.x, d.x,  fmaf(xb.y, d.y,  fmaf(xb.z, d.z,  fmaf(xb.w, d.w,  b3))));
    }
    #pragma unroll
    for (int off = 16; off > 0; off >>= 1) {
        a0 += __shfl_down_sync(0xffffffffu, a0, off);
        a1 += __shfl_down_sync(0xffffffffu, a1, off);
        a2 += __shfl_down_sync(0xffffffffu, a2, off);
        a3 += __shfl_down_sync(0xffffffffu, a3, off);
        b0 += __shfl_down_sync(0xffffffffu, b0, off);
        b1 += __shfl_down_sync(0xffffffffu, b1, off);
        b2 += __shfl_down_sync(0xffffffffu, b2, off);
        b3 += __shfl_down_sync(0xffffffffu, b3, off);
    }
    float cA, cB;
    if (lane == 0) {
        float l0 = a0 + bv[0], l1 = a1 + bv[1], l2 = a2 + bv[2];
        float m  = fmaxf(l0, fmaxf(l1, l2));
        float e0 = expf(l0 - m), e1 = expf(l1 - m), e2 = expf(l2 - m);
        cA = (e0 / (e0 + e1 + e2)) * (1.0f / (1.0f + expf(-a3)));

        float k0 = b0 + bv[0], k1 = b1 + bv[1], k2 = b2 + bv[2];
        float n  = fmaxf(k0, fmaxf(k1, k2));
        float f0 = expf(k0 - n), f1 = expf(k1 - n), f2 = expf(k2 - n);
        cB = (f0 / (f0 + f1 + f2)) * (1.0f / (1.0f + expf(-b3)));
    }
    cA = __shfl_sync(0xffffffffu, cA, 0);
    cB = __shfl_sync(0xffffffffu, cB, 0);

    // Warp 0 writes both 100-float4 c-regions.
    const float4 cvA = make_float4(cA, cA, cA, cA);
    const float4 cvB = make_float4(cB, cB, cB, cB);
    for (int j = lane; j < NCV; j += 32) {
        __stcs(&o[j],         cvA);
        __stcs(&o[SLABV + j], cvB);
    }
}

extern "C" void kernel_launch(void* const* d_in, const int* in_sizes, int n_in,
                              void* d_out, int out_size) {
    const float* hs = (const float*)d_in[0];  // hidden_state [1, 8192, 400]
    const float* W  = (const float*)d_in[1];  // W_ap [3, 400]
    const float* bv = (const float*)d_in[2];  // b_ap [3]
    const float* Dv = (const float*)d_in[3];  // D [1, 400]
    float* out = (float*)d_out;               // [1, 8192, 32, 400]

    StackMemory_kernel<<<TSTEPS / 2, NTHREADS>>>(hs, W, bv, Dv, out);
}